// round 1
// baseline (speedup 1.0000x reference)
#include <cuda_runtime.h>
#include <math.h>

#define NBATCH 4
#define CH     256
#define NPIX   4096
#define KD     32
#define NZ     8   // 2 branches x 4 batches

// ---- scratch (module-load allocated; no runtime alloc) ----
__device__ float g_FG[NZ][2*KD][NPIX];   // f rows [0,32), g rows [32,64)
__device__ float g_H [NZ][CH][NPIX];     // h projection
__device__ float g_S [NZ][NPIX][NPIX];   // scores -> softmax probs (in place)

// =====================================================================
// Generic tiled SGEMM body.  A:[M,K] row-major, B:[K,N] row-major,
// C:[M,N] row-major.  Optional bias[M] (when X==null), optional
// epilogue C = gamma*acc + X (when X!=null).
// Requires: TM%4==0, TN%4==0, all dims divide tiles exactly.
// =====================================================================
template<int BM, int BN, int BK, int TM, int TN>
__device__ __forceinline__ void sgemm_body(
    const float* __restrict__ A, const float* __restrict__ B,
    float* __restrict__ C,
    int K, int ldA, int ldB, int ldC,
    int tileRow, int tileCol,
    const float* __restrict__ bias,
    const float* __restrict__ X, const float* __restrict__ gammaPtr)
{
    constexpr int THREADS = (BM/TM)*(BN/TN);
    __shared__ float As[BK][BM];
    __shared__ float Bs[BK][BN];
    const int tid = threadIdx.x;
    const int tx = tid % (BN/TN);
    const int ty = tid / (BN/TN);

    A += (size_t)tileRow * BM * ldA;
    B += (size_t)tileCol * BN;
    const size_t cOff = (size_t)tileRow * BM * ldC + (size_t)tileCol * BN;
    C += cOff;
    if (X) X += cOff;

    constexpr int AVR = BK/4;                 // float4 per A-tile row
    const int aRow = tid / AVR;
    const int aCol = (tid % AVR)*4;
    constexpr int ARS = THREADS / AVR;
    constexpr int AIT = BM / ARS;

    constexpr int BVR = BN/4;
    const int bRow = tid / BVR;
    const int bCol = (tid % BVR)*4;
    constexpr int BRS = THREADS / BVR;
    constexpr int BIT = BK / BRS;

    float4 aF[AIT], bF[BIT];
#pragma unroll
    for (int i=0;i<AIT;i++)
        aF[i] = *reinterpret_cast<const float4*>(&A[(size_t)(aRow+i*ARS)*ldA + aCol]);
#pragma unroll
    for (int i=0;i<BIT;i++)
        bF[i] = *reinterpret_cast<const float4*>(&B[(size_t)(bRow+i*BRS)*ldB + bCol]);

    float acc[TM][TN];
#pragma unroll
    for (int i=0;i<TM;i++)
#pragma unroll
        for (int j=0;j<TN;j++) acc[i][j] = 0.f;

    for (int kb = 0; kb < K; kb += BK) {
        __syncthreads();
#pragma unroll
        for (int i=0;i<AIT;i++){
            As[aCol+0][aRow+i*ARS] = aF[i].x;
            As[aCol+1][aRow+i*ARS] = aF[i].y;
            As[aCol+2][aRow+i*ARS] = aF[i].z;
            As[aCol+3][aRow+i*ARS] = aF[i].w;
        }
#pragma unroll
        for (int i=0;i<BIT;i++)
            *reinterpret_cast<float4*>(&Bs[bRow+i*BRS][bCol]) = bF[i];
        __syncthreads();

        if (kb + BK < K) {
#pragma unroll
            for (int i=0;i<AIT;i++)
                aF[i] = *reinterpret_cast<const float4*>(
                    &A[(size_t)(aRow+i*ARS)*ldA + (kb+BK) + aCol]);
#pragma unroll
            for (int i=0;i<BIT;i++)
                bF[i] = *reinterpret_cast<const float4*>(
                    &B[(size_t)(kb+BK+bRow+i*BRS)*ldB + bCol]);
        }

#pragma unroll
        for (int k=0;k<BK;k++){
            float ra[TM], rb[TN];
#pragma unroll
            for (int i=0;i<TM;i+=4){
                float4 v = *reinterpret_cast<const float4*>(&As[k][ty*TM+i]);
                ra[i]=v.x; ra[i+1]=v.y; ra[i+2]=v.z; ra[i+3]=v.w;
            }
#pragma unroll
            for (int j=0;j<TN;j+=4){
                float4 v = *reinterpret_cast<const float4*>(&Bs[k][tx*TN+j]);
                rb[j]=v.x; rb[j+1]=v.y; rb[j+2]=v.z; rb[j+3]=v.w;
            }
#pragma unroll
            for (int i=0;i<TM;i++)
#pragma unroll
                for (int j=0;j<TN;j++)
                    acc[i][j] = fmaf(ra[i], rb[j], acc[i][j]);
        }
    }

    const float gamma = gammaPtr ? *gammaPtr : 0.f;
#pragma unroll
    for (int i=0;i<TM;i++){
        const int row = ty*TM + i;
        const float bv = bias ? bias[tileRow*BM + row] : 0.f;
#pragma unroll
        for (int j=0;j<TN;j+=4){
            const int col = tx*TN + j;
            float4 o;
            if (X) {
                const float4 xv = *reinterpret_cast<const float4*>(&X[(size_t)row*ldC + col]);
                o.x = fmaf(gamma, acc[i][j+0], xv.x);
                o.y = fmaf(gamma, acc[i][j+1], xv.y);
                o.z = fmaf(gamma, acc[i][j+2], xv.z);
                o.w = fmaf(gamma, acc[i][j+3], xv.w);
            } else {
                o.x = acc[i][j+0] + bv;
                o.y = acc[i][j+1] + bv;
                o.z = acc[i][j+2] + bv;
                o.w = acc[i][j+3] + bv;
            }
            *reinterpret_cast<float4*>(&C[(size_t)row*ldC + col]) = o;
        }
    }
}

// =====================================================================
// Kernel 1: f/g projections.  grid (32, 2, 8), 256 threads
//   g_FG[z][fg*32 + k][n] = sum_c W[k][c]*x[b][c][n] + bias[k]
// =====================================================================
__global__ __launch_bounds__(256) void proj_fg_kernel(
    const float* __restrict__ x1, const float* __restrict__ x2,
    const float* __restrict__ f_w, const float* __restrict__ f_b,
    const float* __restrict__ g_w, const float* __restrict__ g_b)
{
    const int z  = blockIdx.z;
    const int br = z >> 2, b = z & 3;
    const int fg = blockIdx.y;
    const float* W    = fg ? g_w : f_w;
    const float* bias = fg ? g_b : f_b;
    const float* X    = (br ? x2 : x1) + (size_t)b * CH * NPIX;
    float* C = &g_FG[z][fg*KD][0];
    sgemm_body<32,128,32,4,4>(W, X, C, CH, CH, NPIX, NPIX,
                              0, blockIdx.x, bias, nullptr, nullptr);
}

// =====================================================================
// Kernel 2: h projection.  grid (32, 2, 8), 256 threads
// =====================================================================
__global__ __launch_bounds__(256) void proj_h_kernel(
    const float* __restrict__ x1, const float* __restrict__ x2,
    const float* __restrict__ h1w, const float* __restrict__ h1b,
    const float* __restrict__ h2w, const float* __restrict__ h2b)
{
    const int z  = blockIdx.z;
    const int br = z >> 2, b = z & 3;
    const float* W    = br ? h2w : h1w;
    const float* bias = br ? h2b : h1b;
    const float* X    = (br ? x2 : x1) + (size_t)b * CH * NPIX;
    sgemm_body<128,128,8,8,8>(W, X, &g_H[z][0][0], CH, CH, NPIX, NPIX,
                              blockIdx.y, blockIdx.x, bias, nullptr, nullptr);
}

// =====================================================================
// Kernel 3: scores  S[z][n][m] = (1/sqrt(32)) * sum_k f[k][n]*g[k][m]
// grid (32 m-tiles, 32 n-tiles, 8), 256 threads, K=32 fully unrolled
// =====================================================================
__global__ __launch_bounds__(256) void scores_kernel()
{
    const int z = blockIdx.z;
    __shared__ float Fs[KD][128];
    __shared__ float Gs[KD][128];
    const int tid = threadIdx.x;
    const float* F = &g_FG[z][0][0];          // [64][4096]
    const int nBase = blockIdx.y * 128;
    const int mBase = blockIdx.x * 128;

    const int c4 = (tid % 32) * 4;
    const int r0 = tid / 32;                  // 0..7
#pragma unroll
    for (int i=0;i<4;i++){
        const int k = r0 + i*8;
        *reinterpret_cast<float4*>(&Fs[k][c4]) =
            *reinterpret_cast<const float4*>(&F[(size_t)k*NPIX + nBase + c4]);
        *reinterpret_cast<float4*>(&Gs[k][c4]) =
            *reinterpret_cast<const float4*>(&F[(size_t)(KD+k)*NPIX + mBase + c4]);
    }
    __syncthreads();

    const int tx = tid % 16, ty = tid / 16;
    float acc[8][8];
#pragma unroll
    for (int i=0;i<8;i++)
#pragma unroll
        for (int j=0;j<8;j++) acc[i][j]=0.f;

#pragma unroll
    for (int k=0;k<KD;k++){
        float ra[8], rb[8];
        float4 a0 = *reinterpret_cast<const float4*>(&Fs[k][ty*8]);
        float4 a1 = *reinterpret_cast<const float4*>(&Fs[k][ty*8+4]);
        float4 b0 = *reinterpret_cast<const float4*>(&Gs[k][tx*8]);
        float4 b1 = *reinterpret_cast<const float4*>(&Gs[k][tx*8+4]);
        ra[0]=a0.x; ra[1]=a0.y; ra[2]=a0.z; ra[3]=a0.w;
        ra[4]=a1.x; ra[5]=a1.y; ra[6]=a1.z; ra[7]=a1.w;
        rb[0]=b0.x; rb[1]=b0.y; rb[2]=b0.z; rb[3]=b0.w;
        rb[4]=b1.x; rb[5]=b1.y; rb[6]=b1.z; rb[7]=b1.w;
#pragma unroll
        for (int i=0;i<8;i++)
#pragma unroll
            for (int j=0;j<8;j++)
                acc[i][j] = fmaf(ra[i], rb[j], acc[i][j]);
    }

    const float scale = 0.17677669529663688f;   // 1/sqrt(32)
#pragma unroll
    for (int i=0;i<8;i++){
        const int n = nBase + ty*8 + i;
        float* Sr = &g_S[z][n][0];
#pragma unroll
        for (int j=0;j<8;j+=4){
            const int m = mBase + tx*8 + j;
            float4 o;
            o.x = acc[i][j+0]*scale;
            o.y = acc[i][j+1]*scale;
            o.z = acc[i][j+2]*scale;
            o.w = acc[i][j+3]*scale;
            *reinterpret_cast<float4*>(&Sr[m]) = o;
        }
    }
}

// =====================================================================
// Kernel 4: row softmax over m (in place).  grid (4096, 8), 256 threads
// =====================================================================
__global__ __launch_bounds__(256) void softmax_kernel()
{
    const int z = blockIdx.y;
    const int n = blockIdx.x;
    float* row = &g_S[z][n][0];
    const int tid = threadIdx.x;
    const int lane = tid & 31, w = tid >> 5;
    __shared__ float red[8];

    float v[16];
#pragma unroll
    for (int i=0;i<16;i++) v[i] = row[tid + i*256];

    float m = -3.4e38f;
#pragma unroll
    for (int i=0;i<16;i++) m = fmaxf(m, v[i]);
#pragma unroll
    for (int o=16;o>0;o>>=1) m = fmaxf(m, __shfl_xor_sync(0xffffffffu, m, o));
    if (lane == 0) red[w] = m;
    __syncthreads();
    float bm = red[0];
#pragma unroll
    for (int i=1;i<8;i++) bm = fmaxf(bm, red[i]);
    __syncthreads();

    float s = 0.f;
#pragma unroll
    for (int i=0;i<16;i++){ v[i] = __expf(v[i] - bm); s += v[i]; }
#pragma unroll
    for (int o=16;o>0;o>>=1) s += __shfl_xor_sync(0xffffffffu, s, o);
    if (lane == 0) red[w] = s;
    __syncthreads();
    float tot = 0.f;
#pragma unroll
    for (int i=0;i<8;i++) tot += red[i];
    const float inv = 1.0f / tot;

#pragma unroll
    for (int i=0;i<16;i++) row[tid + i*256] = v[i] * inv;
}

// =====================================================================
// Kernel 5: out[z] = gamma * (H[z] @ P[z]) + x.  grid (32, 2, 8)
// =====================================================================
__global__ __launch_bounds__(256) void out_kernel(
    const float* __restrict__ x1, const float* __restrict__ x2,
    const float* __restrict__ gamma1, const float* __restrict__ gamma2,
    float* __restrict__ out)
{
    const int z  = blockIdx.z;
    const int br = z >> 2, b = z & 3;
    const float* X  = (br ? x2 : x1) + (size_t)b * CH * NPIX;
    const float* gp = br ? gamma2 : gamma1;
    float* C = out + (size_t)z * CH * NPIX;
    sgemm_body<128,128,8,8,8>(&g_H[z][0][0], &g_S[z][0][0], C,
                              NPIX, NPIX, NPIX, NPIX,
                              blockIdx.y, blockIdx.x, nullptr, X, gp);
}

// =====================================================================
extern "C" void kernel_launch(void* const* d_in, const int* in_sizes, int n_in,
                              void* d_out, int out_size)
{
    const float* x1     = (const float*)d_in[0];
    const float* x2     = (const float*)d_in[1];
    const float* f_w    = (const float*)d_in[2];
    const float* f_b    = (const float*)d_in[3];
    const float* g_w    = (const float*)d_in[4];
    const float* g_b    = (const float*)d_in[5];
    const float* h1_w   = (const float*)d_in[6];
    const float* h1_b   = (const float*)d_in[7];
    const float* h2_w   = (const float*)d_in[8];
    const float* h2_b   = (const float*)d_in[9];
    const float* gamma1 = (const float*)d_in[10];
    const float* gamma2 = (const float*)d_in[11];
    float* out = (float*)d_out;

    proj_fg_kernel<<<dim3(32, 2, NZ), 256>>>(x1, x2, f_w, f_b, g_w, g_b);
    proj_h_kernel <<<dim3(32, 2, NZ), 256>>>(x1, x2, h1_w, h1_b, h2_w, h2_b);
    scores_kernel <<<dim3(32, 32, NZ), 256>>>();
    softmax_kernel<<<dim3(NPIX, NZ), 256>>>();
    out_kernel    <<<dim3(32, 2, NZ), 256>>>(x1, x2, gamma1, gamma2, out);
}

// round 3
// speedup vs baseline: 2.3966x; 2.3966x over previous
#include <cuda_runtime.h>
#include <cuda_bf16.h>
#include <cstdint>
#include <math.h>

#define NBATCH 4
#define CH     256
#define NPIX   4096
#define KD     32
#define NZ     8   // 2 branches x 4 batches

// ---- scratch (module-load allocated; no runtime alloc) ----
__device__ float g_FG[NZ][2*KD][NPIX];               // f rows [0,32), g rows [32,64)
__device__ float g_S [NZ][NPIX][NPIX];               // scores fp32; softmax rewrites each row in place as bf16 P
__device__ __nv_bfloat16 g_Hb[NZ][CH][NPIX];         // h projection, bf16
__device__ __nv_bfloat16 g_Pt[NZ][NPIX][NPIX];       // P^T bf16: Pt[m][n]

__device__ __forceinline__ uint32_t smem_u32(const void* p) {
    uint32_t a;
    asm("{ .reg .u64 t; cvta.to.shared.u64 t, %1; cvt.u32.u64 %0, t; }" : "=r"(a) : "l"(p));
    return a;
}

#define CP_ASYNC16(dst, src) \
    asm volatile("cp.async.cg.shared.global [%0], [%1], 16;" :: "r"(dst), "l"(src))
#define CP_ASYNC_COMMIT() asm volatile("cp.async.commit_group;" ::: "memory")
#define CP_ASYNC_WAIT_1() asm volatile("cp.async.wait_group 1;" ::: "memory")
#define CP_ASYNC_WAIT_0() asm volatile("cp.async.wait_group 0;" ::: "memory")

#define LDSM_X4(r0,r1,r2,r3,addr) \
    asm volatile("ldmatrix.sync.aligned.m8n8.x4.shared.b16 {%0,%1,%2,%3}, [%4];" \
        : "=r"(r0), "=r"(r1), "=r"(r2), "=r"(r3) : "r"(addr))

#define MMA_BF16(c0,c1,c2,c3,a0,a1,a2,a3,b0,b1) \
    asm volatile("mma.sync.aligned.m16n8k16.row.col.f32.bf16.bf16.f32 " \
        "{%0,%1,%2,%3}, {%4,%5,%6,%7}, {%8,%9}, {%0,%1,%2,%3};" \
        : "+f"(c0), "+f"(c1), "+f"(c2), "+f"(c3) \
        : "r"(a0), "r"(a1), "r"(a2), "r"(a3), "r"(b0), "r"(b1))

// =====================================================================
// Generic tiled SGEMM body (SIMT, fp32).  A:[M,K] rm, B:[K,N] rm,
// C:[M,N] rm (OutT float or bf16), bias[M] optional.
// =====================================================================
template<int BM, int BN, int BK, int TM, int TN, typename OutT>
__device__ __forceinline__ void sgemm_body(
    const float* __restrict__ A, const float* __restrict__ B,
    OutT* __restrict__ C,
    int K, int ldA, int ldB, int ldC,
    int tileRow, int tileCol,
    const float* __restrict__ bias)
{
    constexpr int THREADS = (BM/TM)*(BN/TN);
    constexpr bool BF16 = (sizeof(OutT) == 2);
    __shared__ float As[BK][BM];
    __shared__ float Bs[BK][BN];
    const int tid = threadIdx.x;
    const int tx = tid % (BN/TN);
    const int ty = tid / (BN/TN);

    A += (size_t)tileRow * BM * ldA;
    B += (size_t)tileCol * BN;
    C += (size_t)tileRow * BM * ldC + (size_t)tileCol * BN;

    constexpr int AVR = BK/4;
    const int aRow = tid / AVR;
    const int aCol = (tid % AVR)*4;
    constexpr int ARS = THREADS / AVR;
    constexpr int AIT = BM / ARS;

    constexpr int BVR = BN/4;
    const int bRow = tid / BVR;
    const int bCol = (tid % BVR)*4;
    constexpr int BRS = THREADS / BVR;
    constexpr int BIT = BK / BRS;

    float4 aF[AIT], bF[BIT];
#pragma unroll
    for (int i=0;i<AIT;i++)
        aF[i] = *reinterpret_cast<const float4*>(&A[(size_t)(aRow+i*ARS)*ldA + aCol]);
#pragma unroll
    for (int i=0;i<BIT;i++)
        bF[i] = *reinterpret_cast<const float4*>(&B[(size_t)(bRow+i*BRS)*ldB + bCol]);

    float acc[TM][TN];
#pragma unroll
    for (int i=0;i<TM;i++)
#pragma unroll
        for (int j=0;j<TN;j++) acc[i][j] = 0.f;

    for (int kb = 0; kb < K; kb += BK) {
        __syncthreads();
#pragma unroll
        for (int i=0;i<AIT;i++){
            As[aCol+0][aRow+i*ARS] = aF[i].x;
            As[aCol+1][aRow+i*ARS] = aF[i].y;
            As[aCol+2][aRow+i*ARS] = aF[i].z;
            As[aCol+3][aRow+i*ARS] = aF[i].w;
        }
#pragma unroll
        for (int i=0;i<BIT;i++)
            *reinterpret_cast<float4*>(&Bs[bRow+i*BRS][bCol]) = bF[i];
        __syncthreads();

        if (kb + BK < K) {
#pragma unroll
            for (int i=0;i<AIT;i++)
                aF[i] = *reinterpret_cast<const float4*>(
                    &A[(size_t)(aRow+i*ARS)*ldA + (kb+BK) + aCol]);
#pragma unroll
            for (int i=0;i<BIT;i++)
                bF[i] = *reinterpret_cast<const float4*>(
                    &B[(size_t)(kb+BK+bRow+i*BRS)*ldB + bCol]);
        }

#pragma unroll
        for (int k=0;k<BK;k++){
            float ra[TM], rb[TN];
#pragma unroll
            for (int i=0;i<TM;i+=4){
                float4 v = *reinterpret_cast<const float4*>(&As[k][ty*TM+i]);
                ra[i]=v.x; ra[i+1]=v.y; ra[i+2]=v.z; ra[i+3]=v.w;
            }
#pragma unroll
            for (int j=0;j<TN;j+=4){
                float4 v = *reinterpret_cast<const float4*>(&Bs[k][tx*TN+j]);
                rb[j]=v.x; rb[j+1]=v.y; rb[j+2]=v.z; rb[j+3]=v.w;
            }
#pragma unroll
            for (int i=0;i<TM;i++)
#pragma unroll
                for (int j=0;j<TN;j++)
                    acc[i][j] = fmaf(ra[i], rb[j], acc[i][j]);
        }
    }

#pragma unroll
    for (int i=0;i<TM;i++){
        const int row = ty*TM + i;
        const float bv = bias ? bias[tileRow*BM + row] : 0.f;
#pragma unroll
        for (int j=0;j<TN;j+=4){
            const int col = tx*TN + j;
            float4 o;
            o.x = acc[i][j+0] + bv;
            o.y = acc[i][j+1] + bv;
            o.z = acc[i][j+2] + bv;
            o.w = acc[i][j+3] + bv;
            if constexpr (!BF16) {
                *reinterpret_cast<float4*>(&C[(size_t)row*ldC + col]) = o;
            } else {
                __nv_bfloat162 p0 = __float22bfloat162_rn(make_float2(o.x, o.y));
                __nv_bfloat162 p1 = __float22bfloat162_rn(make_float2(o.z, o.w));
                uint2 u;
                u.x = reinterpret_cast<uint32_t&>(p0);
                u.y = reinterpret_cast<uint32_t&>(p1);
                *reinterpret_cast<uint2*>(&C[(size_t)row*ldC + col]) = u;
            }
        }
    }
}

// =====================================================================
// Kernel 1: f/g projections (fp32 out)
// =====================================================================
__global__ __launch_bounds__(256) void proj_fg_kernel(
    const float* __restrict__ x1, const float* __restrict__ x2,
    const float* __restrict__ f_w, const float* __restrict__ f_b,
    const float* __restrict__ g_w, const float* __restrict__ g_b)
{
    const int z  = blockIdx.z;
    const int br = z >> 2, b = z & 3;
    const int fg = blockIdx.y;
    const float* W    = fg ? g_w : f_w;
    const float* bias = fg ? g_b : f_b;
    const float* X    = (br ? x2 : x1) + (size_t)b * CH * NPIX;
    float* C = &g_FG[z][fg*KD][0];
    sgemm_body<32,128,32,4,4,float>(W, X, C, CH, CH, NPIX, NPIX,
                                    0, blockIdx.x, bias);
}

// =====================================================================
// Kernel 2: h projection -> bf16
// =====================================================================
__global__ __launch_bounds__(256) void proj_h_kernel(
    const float* __restrict__ x1, const float* __restrict__ x2,
    const float* __restrict__ h1w, const float* __restrict__ h1b,
    const float* __restrict__ h2w, const float* __restrict__ h2b)
{
    const int z  = blockIdx.z;
    const int br = z >> 2, b = z & 3;
    const float* W    = br ? h2w : h1w;
    const float* bias = br ? h2b : h1b;
    const float* X    = (br ? x2 : x1) + (size_t)b * CH * NPIX;
    sgemm_body<128,128,8,8,8,__nv_bfloat16>(W, X, &g_Hb[z][0][0], CH, CH, NPIX, NPIX,
                                            blockIdx.y, blockIdx.x, bias);
}

// =====================================================================
// Kernel 3: scores  S[z][n][m] = (1/sqrt(32)) * sum_k f[k][n]*g[k][m]
// =====================================================================
__global__ __launch_bounds__(256) void scores_kernel()
{
    const int z = blockIdx.z;
    __shared__ float Fs[KD][128];
    __shared__ float Gs[KD][128];
    const int tid = threadIdx.x;
    const float* F = &g_FG[z][0][0];
    const int nBase = blockIdx.y * 128;
    const int mBase = blockIdx.x * 128;

    const int c4 = (tid % 32) * 4;
    const int r0 = tid / 32;
#pragma unroll
    for (int i=0;i<4;i++){
        const int k = r0 + i*8;
        *reinterpret_cast<float4*>(&Fs[k][c4]) =
            *reinterpret_cast<const float4*>(&F[(size_t)k*NPIX + nBase + c4]);
        *reinterpret_cast<float4*>(&Gs[k][c4]) =
            *reinterpret_cast<const float4*>(&F[(size_t)(KD+k)*NPIX + mBase + c4]);
    }
    __syncthreads();

    const int tx = tid % 16, ty = tid / 16;
    float acc[8][8];
#pragma unroll
    for (int i=0;i<8;i++)
#pragma unroll
        for (int j=0;j<8;j++) acc[i][j]=0.f;

#pragma unroll
    for (int k=0;k<KD;k++){
        float ra[8], rb[8];
        float4 a0 = *reinterpret_cast<const float4*>(&Fs[k][ty*8]);
        float4 a1 = *reinterpret_cast<const float4*>(&Fs[k][ty*8+4]);
        float4 b0 = *reinterpret_cast<const float4*>(&Gs[k][tx*8]);
        float4 b1 = *reinterpret_cast<const float4*>(&Gs[k][tx*8+4]);
        ra[0]=a0.x; ra[1]=a0.y; ra[2]=a0.z; ra[3]=a0.w;
        ra[4]=a1.x; ra[5]=a1.y; ra[6]=a1.z; ra[7]=a1.w;
        rb[0]=b0.x; rb[1]=b0.y; rb[2]=b0.z; rb[3]=b0.w;
        rb[4]=b1.x; rb[5]=b1.y; rb[6]=b1.z; rb[7]=b1.w;
#pragma unroll
        for (int i=0;i<8;i++)
#pragma unroll
            for (int j=0;j<8;j++)
                acc[i][j] = fmaf(ra[i], rb[j], acc[i][j]);
    }

    const float scale = 0.17677669529663688f;   // 1/sqrt(32)
#pragma unroll
    for (int i=0;i<8;i++){
        const int n = nBase + ty*8 + i;
        float* Sr = &g_S[z][n][0];
#pragma unroll
        for (int j=0;j<8;j+=4){
            const int m = mBase + tx*8 + j;
            float4 o;
            o.x = acc[i][j+0]*scale;
            o.y = acc[i][j+1]*scale;
            o.z = acc[i][j+2]*scale;
            o.w = acc[i][j+3]*scale;
            *reinterpret_cast<float4*>(&Sr[m]) = o;
        }
    }
}

// =====================================================================
// Kernel 4: row softmax; reads fp32 row, writes bf16 P into the SAME
// row's storage (first half of its 16KB). Row-local aliasing only.
// =====================================================================
__global__ __launch_bounds__(256) void softmax_kernel()
{
    const int z = blockIdx.y;
    const int n = blockIdx.x;
    float* row = &g_S[z][n][0];
    __nv_bfloat16* prow = reinterpret_cast<__nv_bfloat16*>(row);
    const int tid = threadIdx.x;
    const int lane = tid & 31, w = tid >> 5;
    __shared__ float red[8];

    float v[16];
#pragma unroll
    for (int i=0;i<16;i++) v[i] = row[tid + i*256];

    float m = -3.4e38f;
#pragma unroll
    for (int i=0;i<16;i++) m = fmaxf(m, v[i]);
#pragma unroll
    for (int o=16;o>0;o>>=1) m = fmaxf(m, __shfl_xor_sync(0xffffffffu, m, o));
    if (lane == 0) red[w] = m;
    __syncthreads();
    float bm = red[0];
#pragma unroll
    for (int i=1;i<8;i++) bm = fmaxf(bm, red[i]);
    __syncthreads();

    float s = 0.f;
#pragma unroll
    for (int i=0;i<16;i++){ v[i] = __expf(v[i] - bm); s += v[i]; }
#pragma unroll
    for (int o=16;o>0;o>>=1) s += __shfl_xor_sync(0xffffffffu, s, o);
    if (lane == 0) red[w] = s;
    __syncthreads();
    float tot = 0.f;
#pragma unroll
    for (int i=0;i<8;i++) tot += red[i];
    const float inv = 1.0f / tot;

#pragma unroll
    for (int i=0;i<16;i++)
        prow[tid + i*256] = __float2bfloat16(v[i] * inv);
}

// =====================================================================
// Kernel 5: transpose P (bf16, row stride 8192 inside g_S) -> Pt[m][n]
// =====================================================================
__global__ __launch_bounds__(256) void transpose_kernel()
{
    const int z  = blockIdx.z;
    const int m0 = blockIdx.x * 64;
    const int n0 = blockIdx.y * 64;
    const __nv_bfloat16* P = reinterpret_cast<const __nv_bfloat16*>(&g_S[z][0][0]);
    __shared__ unsigned short t[64][66];
    const int tid = threadIdx.x;
    const int rr = tid >> 4;
    const int c4 = (tid & 15) * 4;

#pragma unroll
    for (int p=0;p<4;p++){
        const int row = rr + p*16;                       // n local
        uint2 v = *reinterpret_cast<const uint2*>(
            &P[(size_t)(n0 + row) * 8192 + m0 + c4]);
        t[row][c4+0] = (unsigned short)(v.x & 0xffff);
        t[row][c4+1] = (unsigned short)(v.x >> 16);
        t[row][c4+2] = (unsigned short)(v.y & 0xffff);
        t[row][c4+3] = (unsigned short)(v.y >> 16);
    }
    __syncthreads();

#pragma unroll
    for (int p=0;p<4;p++){
        const int orow = rr + p*16;                      // m local
        uint2 u;
        u.x = (uint32_t)t[c4+0][orow] | ((uint32_t)t[c4+1][orow] << 16);
        u.y = (uint32_t)t[c4+2][orow] | ((uint32_t)t[c4+3][orow] << 16);
        *reinterpret_cast<uint2*>(&g_Pt[z][m0 + orow][n0 + c4]) = u;
    }
}

// =====================================================================
// Kernel 6: out[z] = gamma * (H @ P) + x  via mma.sync bf16 (HMMA).
// CTA tile 128(c) x 128(m), BK=64, 8 warps of 64x32, cp.async double buffer.
// A = g_Hb[c][k] row-major, B = g_Pt[m][k] (= P col-major). rel layout:
//   SMEM padded rows of 72 bf16 (144B) -> conflict-free ldmatrix.
// =====================================================================
#define BK      64
#define LDSS    72                       // padded row, elems
#define BUFB    (128*LDSS*2)             // one operand stage, bytes (18432)
#define OUT_SMEM (4*BUFB)                // A0,A1,B0,B1

__global__ __launch_bounds__(256) void out_mma_kernel(
    const float* __restrict__ x1, const float* __restrict__ x2,
    const float* __restrict__ gamma1, const float* __restrict__ gamma2,
    float* __restrict__ out)
{
    extern __shared__ char sm[];
    const uint32_t smBase = smem_u32(sm);

    const int tid = threadIdx.x;
    const int wid = tid >> 5, lane = tid & 31;
    const int z = blockIdx.z, br = z >> 2, b = z & 3;
    const int mBase = blockIdx.x * 128;
    const int cBase = blockIdx.y * 128;
    const float* X = (br ? x2 : x1) + (size_t)b * CH * NPIX;
    const float gamma = (br ? gamma2 : gamma1)[0];

    // ---- global->smem loader mapping: 2 threads per row, 32 elems each ----
    const int lrow = tid >> 1;
    const int lcol = (tid & 1) * 32;
    const char* gAp = (const char*)(&g_Hb[z][cBase + lrow][lcol]);
    const char* gBp = (const char*)(&g_Pt[z][mBase + lrow][lcol]);
    const uint32_t dA = smBase + (uint32_t)((lrow*LDSS + lcol)*2);
    const uint32_t dB = dA + 2*BUFB;

    // ---- ldmatrix per-lane addresses (stage 0 base) ----
    const int warpM = wid >> 2;          // 0..1 (c dim, 64 rows)
    const int warpN = wid & 3;           // 0..3 (m dim, 32 cols)
    const int lm  = lane & 15;
    const int aco = (lane >= 16) ? 8 : 0;
    uint32_t aAddr[4];
#pragma unroll
    for (int mt=0; mt<4; mt++)
        aAddr[mt] = smBase + (uint32_t)(((warpM*64 + mt*16 + lm)*LDSS + aco)*2);
    const int bro = (lane & 7) + ((lane >= 16) ? 8 : 0);
    const int bco = (lane & 8) ? 8 : 0;
    uint32_t bAddr[2];
#pragma unroll
    for (int p=0; p<2; p++)
        bAddr[p] = smBase + 2*BUFB + (uint32_t)(((warpN*32 + p*16 + bro)*LDSS + bco)*2);

    float acc[4][4][4];
#pragma unroll
    for (int i=0;i<4;i++)
#pragma unroll
        for (int j=0;j<4;j++)
#pragma unroll
            for (int k=0;k<4;k++) acc[i][j][k] = 0.f;

    // ---- prologue: stage 0 ----
    {
        const char* sa = gAp;
        const char* sb = gBp;
#pragma unroll
        for (int j=0;j<4;j++) CP_ASYNC16(dA + j*16, sa + j*16);
#pragma unroll
        for (int j=0;j<4;j++) CP_ASYNC16(dB + j*16, sb + j*16);
        CP_ASYNC_COMMIT();
    }

    for (int it = 0; it < NPIX/BK; ++it) {
        const int s = it & 1;
        if (it + 1 < NPIX/BK) {
            const uint32_t off = (uint32_t)((it+1) & 1) * BUFB;
            const char* sa = gAp + (size_t)(it+1) * (BK*2);
            const char* sb = gBp + (size_t)(it+1) * (BK*2);
#pragma unroll
            for (int j=0;j<4;j++) CP_ASYNC16(dA + off + j*16, sa + j*16);
#pragma unroll
            for (int j=0;j<4;j++) CP_ASYNC16(dB + off + j*16, sb + j*16);
            CP_ASYNC_COMMIT();
            CP_ASYNC_WAIT_1();
        } else {
            CP_ASYNC_WAIT_0();
        }
        __syncthreads();

        const uint32_t so = (uint32_t)s * BUFB;
#pragma unroll
        for (int ks = 0; ks < 4; ++ks) {
            uint32_t a[4][4];
#pragma unroll
            for (int mt=0; mt<4; mt++)
                LDSM_X4(a[mt][0], a[mt][1], a[mt][2], a[mt][3],
                        aAddr[mt] + so + ks*32);
            uint32_t bb[2][4];
#pragma unroll
            for (int p=0; p<2; p++)
                LDSM_X4(bb[p][0], bb[p][1], bb[p][2], bb[p][3],
                        bAddr[p] + so + ks*32);
#pragma unroll
            for (int mt=0; mt<4; mt++)
#pragma unroll
                for (int nt=0; nt<4; nt++) {
                    const uint32_t b0 = bb[nt>>1][(nt&1)*2];
                    const uint32_t b1 = bb[nt>>1][(nt&1)*2+1];
                    MMA_BF16(acc[mt][nt][0], acc[mt][nt][1],
                             acc[mt][nt][2], acc[mt][nt][3],
                             a[mt][0], a[mt][1], a[mt][2], a[mt][3], b0, b1);
                }
        }
        __syncthreads();
    }

    // ---- epilogue: out = gamma*acc + x ----
    const int g  = lane >> 2;
    const int tq = lane & 3;
    float* Cz = out + (size_t)z * CH * NPIX;
#pragma unroll
    for (int mt=0; mt<4; mt++) {
        const int row = cBase + warpM*64 + mt*16 + g;
#pragma unroll
        for (int nt=0; nt<4; nt++) {
            const int col = mBase + warpN*32 + nt*8 + tq*2;
            {
                const float2 xv = *reinterpret_cast<const float2*>(
                    &X[(size_t)row*NPIX + col]);
                float2 o;
                o.x = fmaf(gamma, acc[mt][nt][0], xv.x);
                o.y = fmaf(gamma, acc[mt][nt][1], xv.y);
                *reinterpret_cast<float2*>(&Cz[(size_t)row*NPIX + col]) = o;
            }
            {
                const float2 xv = *reinterpret_cast<const float2*>(
                    &X[(size_t)(row+8)*NPIX + col]);
                float2 o;
                o.x = fmaf(gamma, acc[mt][nt][2], xv.x);
                o.y = fmaf(gamma, acc[mt][nt][3], xv.y);
                *reinterpret_cast<float2*>(&Cz[(size_t)(row+8)*NPIX + col]) = o;
            }
        }
    }
}

// =====================================================================
extern "C" void kernel_launch(void* const* d_in, const int* in_sizes, int n_in,
                              void* d_out, int out_size)
{
    const float* x1     = (const float*)d_in[0];
    const float* x2     = (const float*)d_in[1];
    const float* f_w    = (const float*)d_in[2];
    const float* f_b    = (const float*)d_in[3];
    const float* g_w    = (const float*)d_in[4];
    const float* g_b    = (const float*)d_in[5];
    const float* h1_w   = (const float*)d_in[6];
    const float* h1_b   = (const float*)d_in[7];
    const float* h2_w   = (const float*)d_in[8];
    const float* h2_b   = (const float*)d_in[9];
    const float* gamma1 = (const float*)d_in[10];
    const float* gamma2 = (const float*)d_in[11];
    float* out = (float*)d_out;

    cudaFuncSetAttribute(out_mma_kernel,
                         cudaFuncAttributeMaxDynamicSharedMemorySize, OUT_SMEM);

    proj_fg_kernel  <<<dim3(32, 2, NZ), 256>>>(x1, x2, f_w, f_b, g_w, g_b);
    proj_h_kernel   <<<dim3(32, 2, NZ), 256>>>(x1, x2, h1_w, h1_b, h2_w, h2_b);
    scores_kernel   <<<dim3(32, 32, NZ), 256>>>();
    softmax_kernel  <<<dim3(NPIX, NZ), 256>>>();
    transpose_kernel<<<dim3(64, 64, NZ), 256>>>();
    out_mma_kernel  <<<dim3(32, 2, NZ), 256, OUT_SMEM>>>(x1, x2, gamma1, gamma2, out);
}

// round 4
// speedup vs baseline: 3.3657x; 1.4044x over previous
#include <cuda_runtime.h>
#include <cuda_bf16.h>
#include <cstdint>
#include <math.h>

#define NBATCH 4
#define CH     256
#define NPIX   4096
#define KD     32
#define NZ     8   // 2 branches x 4 batches

// ---- scratch (module-load allocated; no runtime alloc) ----
__device__ __nv_bfloat16 g_fT[NZ][NPIX][KD];         // f^T : [n][k] bf16
__device__ __nv_bfloat16 g_gT[NZ][NPIX][KD];         // g^T : [m][k] bf16
__device__ float         g_invsum[NZ][NPIX];         // 1 / softmax row sum
__device__ __nv_bfloat16 g_Hb[NZ][CH][NPIX];         // h projection (pre-scaled by invsum), bf16
__device__ __nv_bfloat16 g_Pt[NZ][NPIX][NPIX];       // unnormalized P^T bf16: Pt[m][n] = exp(s-max)

__device__ __forceinline__ uint32_t smem_u32(const void* p) {
    uint32_t a;
    asm("{ .reg .u64 t; cvta.to.shared.u64 t, %1; cvt.u32.u64 %0, t; }" : "=r"(a) : "l"(p));
    return a;
}

__device__ __forceinline__ float ex2f(float x) {
    float r;
    asm("ex2.approx.f32 %0, %1;" : "=f"(r) : "f"(x));
    return r;
}

#define CP_ASYNC16(dst, src) \
    asm volatile("cp.async.cg.shared.global [%0], [%1], 16;" :: "r"(dst), "l"(src))
#define CP_ASYNC_COMMIT() asm volatile("cp.async.commit_group;" ::: "memory")
#define CP_ASYNC_WAIT_1() asm volatile("cp.async.wait_group 1;" ::: "memory")
#define CP_ASYNC_WAIT_0() asm volatile("cp.async.wait_group 0;" ::: "memory")

#define LDSM_X4(r0,r1,r2,r3,addr) \
    asm volatile("ldmatrix.sync.aligned.m8n8.x4.shared.b16 {%0,%1,%2,%3}, [%4];" \
        : "=r"(r0), "=r"(r1), "=r"(r2), "=r"(r3) : "r"(addr))

#define MMA_BF16(c0,c1,c2,c3,a0,a1,a2,a3,b0,b1) \
    asm volatile("mma.sync.aligned.m16n8k16.row.col.f32.bf16.bf16.f32 " \
        "{%0,%1,%2,%3}, {%4,%5,%6,%7}, {%8,%9}, {%0,%1,%2,%3};" \
        : "+f"(c0), "+f"(c1), "+f"(c2), "+f"(c3) \
        : "r"(a0), "r"(a1), "r"(a2), "r"(a3), "r"(b0), "r"(b1))

// =====================================================================
// Generic tiled SGEMM body (SIMT, fp32).  A:[M,K] rm, B:[K,N] rm.
// TRANS=false: C:[M,N] rm (float or bf16), optional colScale[N].
// TRANS=true : C is bf16 [Nglobal][KD] and stores C[n][k] = acc^T.
// =====================================================================
template<int BM, int BN, int BK, int TM, int TN, typename OutT, bool TRANS>
__device__ __forceinline__ void sgemm_body(
    const float* __restrict__ A, const float* __restrict__ B,
    OutT* __restrict__ C,
    int K, int ldA, int ldB, int ldC,
    int tileRow, int tileCol,
    const float* __restrict__ bias,
    const float* __restrict__ colScale)
{
    constexpr int THREADS = (BM/TM)*(BN/TN);
    constexpr bool BF16 = (sizeof(OutT) == 2);
    __shared__ float As[BK][BM];
    __shared__ float Bs[BK][BN];
    const int tid = threadIdx.x;
    const int tx = tid % (BN/TN);
    const int ty = tid / (BN/TN);

    A += (size_t)tileRow * BM * ldA;
    B += (size_t)tileCol * BN;
    if (!TRANS)
        C += (size_t)tileRow * BM * ldC + (size_t)tileCol * BN;

    constexpr int AVR = BK/4;
    const int aRow = tid / AVR;
    const int aCol = (tid % AVR)*4;
    constexpr int ARS = THREADS / AVR;
    constexpr int AIT = BM / ARS;

    constexpr int BVR = BN/4;
    const int bRow = tid / BVR;
    const int bCol = (tid % BVR)*4;
    constexpr int BRS = THREADS / BVR;
    constexpr int BIT = BK / BRS;

    float4 aF[AIT], bF[BIT];
#pragma unroll
    for (int i=0;i<AIT;i++)
        aF[i] = *reinterpret_cast<const float4*>(&A[(size_t)(aRow+i*ARS)*ldA + aCol]);
#pragma unroll
    for (int i=0;i<BIT;i++)
        bF[i] = *reinterpret_cast<const float4*>(&B[(size_t)(bRow+i*BRS)*ldB + bCol]);

    float acc[TM][TN];
#pragma unroll
    for (int i=0;i<TM;i++)
#pragma unroll
        for (int j=0;j<TN;j++) acc[i][j] = 0.f;

    for (int kb = 0; kb < K; kb += BK) {
        __syncthreads();
#pragma unroll
        for (int i=0;i<AIT;i++){
            As[aCol+0][aRow+i*ARS] = aF[i].x;
            As[aCol+1][aRow+i*ARS] = aF[i].y;
            As[aCol+2][aRow+i*ARS] = aF[i].z;
            As[aCol+3][aRow+i*ARS] = aF[i].w;
        }
#pragma unroll
        for (int i=0;i<BIT;i++)
            *reinterpret_cast<float4*>(&Bs[bRow+i*BRS][bCol]) = bF[i];
        __syncthreads();

        if (kb + BK < K) {
#pragma unroll
            for (int i=0;i<AIT;i++)
                aF[i] = *reinterpret_cast<const float4*>(
                    &A[(size_t)(aRow+i*ARS)*ldA + (kb+BK) + aCol]);
#pragma unroll
            for (int i=0;i<BIT;i++)
                bF[i] = *reinterpret_cast<const float4*>(
                    &B[(size_t)(kb+BK+bRow+i*BRS)*ldB + bCol]);
        }

#pragma unroll
        for (int k=0;k<BK;k++){
            float ra[TM], rb[TN];
#pragma unroll
            for (int i=0;i<TM;i+=4){
                float4 v = *reinterpret_cast<const float4*>(&As[k][ty*TM+i]);
                ra[i]=v.x; ra[i+1]=v.y; ra[i+2]=v.z; ra[i+3]=v.w;
            }
#pragma unroll
            for (int j=0;j<TN;j+=4){
                float4 v = *reinterpret_cast<const float4*>(&Bs[k][tx*TN+j]);
                rb[j]=v.x; rb[j+1]=v.y; rb[j+2]=v.z; rb[j+3]=v.w;
            }
#pragma unroll
            for (int i=0;i<TM;i++)
#pragma unroll
                for (int j=0;j<TN;j++)
                    acc[i][j] = fmaf(ra[i], rb[j], acc[i][j]);
        }
    }

    if constexpr (TRANS) {
        // transposed bf16 scattered store: C[(n)][k]
#pragma unroll
        for (int i=0;i<TM;i++){
            const int row = tileRow*BM + ty*TM + i;      // k index
            const float bv = bias ? bias[row] : 0.f;
#pragma unroll
            for (int j=0;j<TN;j++){
                const int col = tileCol*BN + tx*TN + j;  // n index
                C[(size_t)col * KD + row] = __float2bfloat16(acc[i][j] + bv);
            }
        }
    } else {
#pragma unroll
        for (int i=0;i<TM;i++){
            const int row = ty*TM + i;
            const float bv = bias ? bias[tileRow*BM + row] : 0.f;
#pragma unroll
            for (int j=0;j<TN;j+=4){
                const int col = tx*TN + j;
                float4 o;
                o.x = acc[i][j+0] + bv;
                o.y = acc[i][j+1] + bv;
                o.z = acc[i][j+2] + bv;
                o.w = acc[i][j+3] + bv;
                if (colScale) {
                    const float4 cs = *reinterpret_cast<const float4*>(
                        &colScale[tileCol*BN + col]);
                    o.x *= cs.x; o.y *= cs.y; o.z *= cs.z; o.w *= cs.w;
                }
                if constexpr (!BF16) {
                    *reinterpret_cast<float4*>(&C[(size_t)row*ldC + col]) = o;
                } else {
                    __nv_bfloat162 p0 = __float22bfloat162_rn(make_float2(o.x, o.y));
                    __nv_bfloat162 p1 = __float22bfloat162_rn(make_float2(o.z, o.w));
                    uint2 u;
                    u.x = reinterpret_cast<uint32_t&>(p0);
                    u.y = reinterpret_cast<uint32_t&>(p1);
                    *reinterpret_cast<uint2*>(&C[(size_t)row*ldC + col]) = u;
                }
            }
        }
    }
}

// =====================================================================
// Kernel 1: f/g projections -> transposed bf16 [n][32]
// =====================================================================
__global__ __launch_bounds__(256) void proj_fg_kernel(
    const float* __restrict__ x1, const float* __restrict__ x2,
    const float* __restrict__ f_w, const float* __restrict__ f_b,
    const float* __restrict__ g_w, const float* __restrict__ g_b)
{
    const int z  = blockIdx.z;
    const int br = z >> 2, b = z & 3;
    const int fg = blockIdx.y;
    const float* W    = fg ? g_w : f_w;
    const float* bias = fg ? g_b : f_b;
    const float* X    = (br ? x2 : x1) + (size_t)b * CH * NPIX;
    __nv_bfloat16* C = fg ? &g_gT[z][0][0] : &g_fT[z][0][0];
    sgemm_body<32,128,32,4,4,__nv_bfloat16,true>(W, X, C, CH, CH, NPIX, 0,
                                                 0, blockIdx.x, bias, nullptr);
}

// =====================================================================
// Kernel 2 (fused): scores (HMMA bf16) + softmax-max/exp + transposed
// bf16 P' write + invsum.  CTA = 64 n-rows x 4096 m.  grid (64, NZ).
// Pass 1: row max only (no exp). Pass 2: p' = exp(s - max), row sums,
// stage transpose in SMEM, write g_Pt[m][n]. Normalization deferred
// to proj_h via g_invsum.
// =====================================================================
#define FLD   40                         // SMEM row stride (elems) for ldmatrix tiles
#define FSM_FT   0u                      // fT: 64 x FLD bf16             (5120 B)
#define FSM_G    5120u                   // g tiles: 2 x 256 x FLD bf16   (2x20480)
#define FSM_GSZ  20480u
#define FSM_ST   46080u                  // stage: 256 x 72 bf16          (36864)
#define FSM_RED  82944u                  // red: 64 x 4 float             (1024)
#define FSM_TOTAL 83968u

__global__ __launch_bounds__(256) void fused_sm_kernel()
{
    extern __shared__ __align__(16) char sm[];
    const uint32_t smBase = smem_u32(sm);
    float* red = reinterpret_cast<float*>(sm + FSM_RED);

    const int tid  = threadIdx.x;
    const int lane = tid & 31, wid = tid >> 5;
    const int z  = blockIdx.y;
    const int n0 = blockIdx.x * 64;
    const int warpM = wid >> 2;          // 0..1  (n, 32 rows each)
    const int warpN = wid & 3;           // 0..3  (m, 64 cols each)
    const int qg = lane >> 2, tq = lane & 3;

    // ---- load fT block: 64 rows x 64B ----
    {
        const int row = tid >> 2, ch = tid & 3;
        CP_ASYNC16(smBase + FSM_FT + (uint32_t)((row*FLD + ch*8)*2),
                   (const char*)&g_fT[z][n0 + row][ch*8]);
    }
    CP_ASYNC_COMMIT();

    // ---- ldmatrix lane addresses ----
    const int lm  = lane & 15;
    const int aco = (lane >= 16) ? 8 : 0;
    uint32_t aAddr[2];
#pragma unroll
    for (int mt=0; mt<2; mt++)
        aAddr[mt] = smBase + FSM_FT +
            (uint32_t)(((warpM*32 + mt*16 + lm)*FLD + aco)*2);
    const int bro = (lane & 7) + ((lane >= 16) ? 8 : 0);
    const int bco = (lane & 8) ? 8 : 0;
    uint32_t bOff[4];
#pragma unroll
    for (int p=0; p<4; p++)
        bOff[p] = (uint32_t)(((warpN*64 + p*16 + bro)*FLD + bco)*2);

    const int grow = tid >> 2, gch = tid & 3;

    float rmax[4], rsum[4];
#pragma unroll
    for (int i=0;i<4;i++){ rmax[i] = -3.4e38f; rsum[i] = 0.f; }

    const float CEXP = 0.17677669529663688f * 1.4426950408889634f; // invsqrt32*log2e

    for (int pass = 0; pass < 2; ++pass) {
        // prologue: g tile 0 -> buf 0
        {
            const char* src = (const char*)&g_gT[z][0][0];
#pragma unroll
            for (int i=0;i<4;i++)
                CP_ASYNC16(smBase + FSM_G + (uint32_t)(((grow+i*64)*FLD + gch*8)*2),
                           src + (size_t)(grow + i*64)*64 + gch*16);
            CP_ASYNC_COMMIT();
        }
        for (int t = 0; t < 16; ++t) {
            if (t < 15) {
                const uint32_t dst = smBase + FSM_G + (uint32_t)((t+1)&1)*FSM_GSZ;
                const char* src = (const char*)&g_gT[z][(t+1)*256][0];
#pragma unroll
                for (int i=0;i<4;i++)
                    CP_ASYNC16(dst + (uint32_t)(((grow+i*64)*FLD + gch*8)*2),
                               src + (size_t)(grow + i*64)*64 + gch*16);
                CP_ASYNC_COMMIT();
                CP_ASYNC_WAIT_1();
            } else {
                CP_ASYNC_WAIT_0();
            }
            __syncthreads();

            const uint32_t gb = smBase + FSM_G + (uint32_t)(t&1)*FSM_GSZ;
            float acc[2][8][4];
#pragma unroll
            for (int mt=0;mt<2;mt++)
#pragma unroll
                for (int nt=0;nt<8;nt++)
#pragma unroll
                    for (int c=0;c<4;c++) acc[mt][nt][c] = 0.f;

#pragma unroll
            for (int ks = 0; ks < 2; ++ks) {
                uint32_t a[2][4];
#pragma unroll
                for (int mt=0; mt<2; mt++)
                    LDSM_X4(a[mt][0], a[mt][1], a[mt][2], a[mt][3],
                            aAddr[mt] + ks*32);
                uint32_t bb[4][4];
#pragma unroll
                for (int p=0; p<4; p++)
                    LDSM_X4(bb[p][0], bb[p][1], bb[p][2], bb[p][3],
                            gb + bOff[p] + ks*32);
#pragma unroll
                for (int mt=0; mt<2; mt++)
#pragma unroll
                    for (int nt=0; nt<8; nt++) {
                        const uint32_t b0 = bb[nt>>1][(nt&1)*2];
                        const uint32_t b1 = bb[nt>>1][(nt&1)*2+1];
                        MMA_BF16(acc[mt][nt][0], acc[mt][nt][1],
                                 acc[mt][nt][2], acc[mt][nt][3],
                                 a[mt][0], a[mt][1], a[mt][2], a[mt][3], b0, b1);
                    }
            }

            if (pass == 0) {
#pragma unroll
                for (int mt=0;mt<2;mt++)
#pragma unroll
                    for (int nt=0;nt<8;nt++)
#pragma unroll
                        for (int c=0;c<4;c++)
                            rmax[mt*2 + (c>>1)] =
                                fmaxf(rmax[mt*2 + (c>>1)], acc[mt][nt][c]);
                __syncthreads();   // protect g buffer reuse
            } else {
                __nv_bfloat16* stg = reinterpret_cast<__nv_bfloat16*>(sm + FSM_ST);
#pragma unroll
                for (int mt=0;mt<2;mt++)
#pragma unroll
                    for (int nt=0;nt<8;nt++)
#pragma unroll
                        for (int c=0;c<4;c++){
                            const int idx = mt*2 + (c>>1);
                            const float p = ex2f((acc[mt][nt][c] - rmax[idx]) * CEXP);
                            rsum[idx] += p;
                            const int ml = warpN*64 + nt*8 + tq*2 + (c&1);
                            const int nl = warpM*32 + mt*16 + qg + (c>>1)*8;
                            stg[ml*72 + nl] = __float2bfloat16(p);
                        }
                __syncthreads();
                // coalesced global write: 256 rows x 128B
                const int ch = tid & 7;
#pragma unroll
                for (int i=0;i<8;i++){
                    const int ml = (tid>>3) + i*32;
                    const uint4 v = *reinterpret_cast<const uint4*>(
                        sm + FSM_ST + (uint32_t)((ml*72 + ch*8)*2));
                    *reinterpret_cast<uint4*>(&g_Pt[z][t*256 + ml][n0 + ch*8]) = v;
                }
            }
        }

        if (pass == 0) {
            // reduce rmax: quad shfl then cross-warpN via SMEM
#pragma unroll
            for (int i=0;i<4;i++){
                float v = rmax[i];
                v = fmaxf(v, __shfl_xor_sync(0xffffffffu, v, 1));
                v = fmaxf(v, __shfl_xor_sync(0xffffffffu, v, 2));
                rmax[i] = v;
            }
            if (tq == 0) {
#pragma unroll
                for (int i=0;i<4;i++){
                    const int r = warpM*32 + (i>>1)*16 + qg + (i&1)*8;
                    red[r*4 + warpN] = rmax[i];
                }
            }
            __syncthreads();
#pragma unroll
            for (int i=0;i<4;i++){
                const int r = warpM*32 + (i>>1)*16 + qg + (i&1)*8;
                rmax[i] = fmaxf(fmaxf(red[r*4+0], red[r*4+1]),
                                fmaxf(red[r*4+2], red[r*4+3]));
            }
            __syncthreads();
        }
    }

    // ---- reduce rsum, write invsum ----
#pragma unroll
    for (int i=0;i<4;i++){
        float v = rsum[i];
        v += __shfl_xor_sync(0xffffffffu, v, 1);
        v += __shfl_xor_sync(0xffffffffu, v, 2);
        rsum[i] = v;
    }
    __syncthreads();
    if (tq == 0) {
#pragma unroll
        for (int i=0;i<4;i++){
            const int r = warpM*32 + (i>>1)*16 + qg + (i&1)*8;
            red[r*4 + warpN] = rsum[i];
        }
    }
    __syncthreads();
    if (warpN == 0 && tq == 0) {
#pragma unroll
        for (int i=0;i<4;i++){
            const int r = warpM*32 + (i>>1)*16 + qg + (i&1)*8;
            const float s = red[r*4+0] + red[r*4+1] + red[r*4+2] + red[r*4+3];
            g_invsum[z][n0 + r] = 1.0f / s;
        }
    }
}

// =====================================================================
// Kernel 3: h projection -> bf16, columns scaled by invsum[n]
// =====================================================================
__global__ __launch_bounds__(256) void proj_h_kernel(
    const float* __restrict__ x1, const float* __restrict__ x2,
    const float* __restrict__ h1w, const float* __restrict__ h1b,
    const float* __restrict__ h2w, const float* __restrict__ h2b)
{
    const int z  = blockIdx.z;
    const int br = z >> 2, b = z & 3;
    const float* W    = br ? h2w : h1w;
    const float* bias = br ? h2b : h1b;
    const float* X    = (br ? x2 : x1) + (size_t)b * CH * NPIX;
    sgemm_body<128,128,8,8,8,__nv_bfloat16,false>(
        W, X, &g_Hb[z][0][0], CH, CH, NPIX, NPIX,
        blockIdx.y, blockIdx.x, bias, &g_invsum[z][0]);
}

// =====================================================================
// Kernel 4: out[z] = gamma * (H' @ P') + x  via mma.sync bf16 (HMMA).
// (unchanged from round 3)
// =====================================================================
#define BK      64
#define LDSS    72
#define BUFB    (128*LDSS*2)
#define OUT_SMEM (4*BUFB)

__global__ __launch_bounds__(256) void out_mma_kernel(
    const float* __restrict__ x1, const float* __restrict__ x2,
    const float* __restrict__ gamma1, const float* __restrict__ gamma2,
    float* __restrict__ out)
{
    extern __shared__ char smo[];
    const uint32_t smBase = smem_u32(smo);

    const int tid = threadIdx.x;
    const int wid = tid >> 5, lane = tid & 31;
    const int z = blockIdx.z, br = z >> 2, b = z & 3;
    const int mBase = blockIdx.x * 128;
    const int cBase = blockIdx.y * 128;
    const float* X = (br ? x2 : x1) + (size_t)b * CH * NPIX;
    const float gamma = (br ? gamma2 : gamma1)[0];

    const int lrow = tid >> 1;
    const int lcol = (tid & 1) * 32;
    const char* gAp = (const char*)(&g_Hb[z][cBase + lrow][lcol]);
    const char* gBp = (const char*)(&g_Pt[z][mBase + lrow][lcol]);
    const uint32_t dA = smBase + (uint32_t)((lrow*LDSS + lcol)*2);
    const uint32_t dB = dA + 2*BUFB;

    const int warpM = wid >> 2;
    const int warpN = wid & 3;
    const int lm  = lane & 15;
    const int aco = (lane >= 16) ? 8 : 0;
    uint32_t aAddr[4];
#pragma unroll
    for (int mt=0; mt<4; mt++)
        aAddr[mt] = smBase + (uint32_t)(((warpM*64 + mt*16 + lm)*LDSS + aco)*2);
    const int bro = (lane & 7) + ((lane >= 16) ? 8 : 0);
    const int bco = (lane & 8) ? 8 : 0;
    uint32_t bAddr[2];
#pragma unroll
    for (int p=0; p<2; p++)
        bAddr[p] = smBase + 2*BUFB + (uint32_t)(((warpN*32 + p*16 + bro)*LDSS + bco)*2);

    float acc[4][4][4];
#pragma unroll
    for (int i=0;i<4;i++)
#pragma unroll
        for (int j=0;j<4;j++)
#pragma unroll
            for (int k=0;k<4;k++) acc[i][j][k] = 0.f;

    {
#pragma unroll
        for (int j=0;j<4;j++) CP_ASYNC16(dA + j*16, gAp + j*16);
#pragma unroll
        for (int j=0;j<4;j++) CP_ASYNC16(dB + j*16, gBp + j*16);
        CP_ASYNC_COMMIT();
    }

    for (int it = 0; it < NPIX/BK; ++it) {
        const int s = it & 1;
        if (it + 1 < NPIX/BK) {
            const uint32_t off = (uint32_t)((it+1) & 1) * BUFB;
            const char* sa = gAp + (size_t)(it+1) * (BK*2);
            const char* sb = gBp + (size_t)(it+1) * (BK*2);
#pragma unroll
            for (int j=0;j<4;j++) CP_ASYNC16(dA + off + j*16, sa + j*16);
#pragma unroll
            for (int j=0;j<4;j++) CP_ASYNC16(dB + off + j*16, sb + j*16);
            CP_ASYNC_COMMIT();
            CP_ASYNC_WAIT_1();
        } else {
            CP_ASYNC_WAIT_0();
        }
        __syncthreads();

        const uint32_t so = (uint32_t)s * BUFB;
#pragma unroll
        for (int ks = 0; ks < 4; ++ks) {
            uint32_t a[4][4];
#pragma unroll
            for (int mt=0; mt<4; mt++)
                LDSM_X4(a[mt][0], a[mt][1], a[mt][2], a[mt][3],
                        aAddr[mt] + so + ks*32);
            uint32_t bb[2][4];
#pragma unroll
            for (int p=0; p<2; p++)
                LDSM_X4(bb[p][0], bb[p][1], bb[p][2], bb[p][3],
                        bAddr[p] + so + ks*32);
#pragma unroll
            for (int mt=0; mt<4; mt++)
#pragma unroll
                for (int nt=0; nt<4; nt++) {
                    const uint32_t b0 = bb[nt>>1][(nt&1)*2];
                    const uint32_t b1 = bb[nt>>1][(nt&1)*2+1];
                    MMA_BF16(acc[mt][nt][0], acc[mt][nt][1],
                             acc[mt][nt][2], acc[mt][nt][3],
                             a[mt][0], a[mt][1], a[mt][2], a[mt][3], b0, b1);
                }
        }
        __syncthreads();
    }

    const int g  = lane >> 2;
    const int tq = lane & 3;
    float* Cz = out + (size_t)z * CH * NPIX;
#pragma unroll
    for (int mt=0; mt<4; mt++) {
        const int row = cBase + warpM*64 + mt*16 + g;
#pragma unroll
        for (int nt=0; nt<4; nt++) {
            const int col = mBase + warpN*32 + nt*8 + tq*2;
            {
                const float2 xv = *reinterpret_cast<const float2*>(
                    &X[(size_t)row*NPIX + col]);
                float2 o;
                o.x = fmaf(gamma, acc[mt][nt][0], xv.x);
                o.y = fmaf(gamma, acc[mt][nt][1], xv.y);
                *reinterpret_cast<float2*>(&Cz[(size_t)row*NPIX + col]) = o;
            }
            {
                const float2 xv = *reinterpret_cast<const float2*>(
                    &X[(size_t)(row+8)*NPIX + col]);
                float2 o;
                o.x = fmaf(gamma, acc[mt][nt][2], xv.x);
                o.y = fmaf(gamma, acc[mt][nt][3], xv.y);
                *reinterpret_cast<float2*>(&Cz[(size_t)(row+8)*NPIX + col]) = o;
            }
        }
    }
}

// =====================================================================
extern "C" void kernel_launch(void* const* d_in, const int* in_sizes, int n_in,
                              void* d_out, int out_size)
{
    const float* x1     = (const float*)d_in[0];
    const float* x2     = (const float*)d_in[1];
    const float* f_w    = (const float*)d_in[2];
    const float* f_b    = (const float*)d_in[3];
    const float* g_w    = (const float*)d_in[4];
    const float* g_b    = (const float*)d_in[5];
    const float* h1_w   = (const float*)d_in[6];
    const float* h1_b   = (const float*)d_in[7];
    const float* h2_w   = (const float*)d_in[8];
    const float* h2_b   = (const float*)d_in[9];
    const float* gamma1 = (const float*)d_in[10];
    const float* gamma2 = (const float*)d_in[11];
    float* out = (float*)d_out;

    cudaFuncSetAttribute(fused_sm_kernel,
                         cudaFuncAttributeMaxDynamicSharedMemorySize, FSM_TOTAL);
    cudaFuncSetAttribute(out_mma_kernel,
                         cudaFuncAttributeMaxDynamicSharedMemorySize, OUT_SMEM);

    proj_fg_kernel <<<dim3(32, 2, NZ), 256>>>(x1, x2, f_w, f_b, g_w, g_b);
    fused_sm_kernel<<<dim3(64, NZ), 256, FSM_TOTAL>>>();
    proj_h_kernel  <<<dim3(32, 2, NZ), 256>>>(x1, x2, h1_w, h1_b, h2_w, h2_b);
    out_mma_kernel <<<dim3(32, 2, NZ), 256, OUT_SMEM>>>(x1, x2, gamma1, gamma2, out);
}

// round 5
// speedup vs baseline: 3.4977x; 1.0392x over previous
#include <cuda_runtime.h>
#include <cuda_bf16.h>
#include <cstdint>
#include <math.h>

#define NBATCH 4
#define CH     256
#define NPIX   4096
#define KD     32
#define NZ     8   // 2 branches x 4 batches

// ---- scratch (module-load allocated; no runtime alloc) ----
__device__ __nv_bfloat16 g_fT[NZ][NPIX][KD];         // f^T : [n][k] bf16
__device__ __nv_bfloat16 g_gT[NZ][NPIX][KD];         // g^T : [m][k] bf16
__device__ float         g_invsum[NZ][NPIX];         // 1 / softmax row sum
__device__ __nv_bfloat16 g_Hb[NZ][CH][NPIX];         // h projection (invsum-scaled), bf16
__device__ __nv_bfloat16 g_Pt[NZ][NPIX][NPIX];       // unnormalized P^T bf16: Pt[m][n]

__device__ __forceinline__ uint32_t smem_u32(const void* p) {
    uint32_t a;
    asm("{ .reg .u64 t; cvta.to.shared.u64 t, %1; cvt.u32.u64 %0, t; }" : "=r"(a) : "l"(p));
    return a;
}

__device__ __forceinline__ float ex2f(float x) {
    float r;
    asm("ex2.approx.f32 %0, %1;" : "=f"(r) : "f"(x));
    return r;
}

#define CP_ASYNC16(dst, src) \
    asm volatile("cp.async.cg.shared.global [%0], [%1], 16;" :: "r"(dst), "l"(src))
#define CP_ASYNC_COMMIT() asm volatile("cp.async.commit_group;" ::: "memory")
#define CP_ASYNC_WAIT_1() asm volatile("cp.async.wait_group 1;" ::: "memory")
#define CP_ASYNC_WAIT_0() asm volatile("cp.async.wait_group 0;" ::: "memory")

#define LDSM_X4(r0,r1,r2,r3,addr) \
    asm volatile("ldmatrix.sync.aligned.m8n8.x4.shared.b16 {%0,%1,%2,%3}, [%4];" \
        : "=r"(r0), "=r"(r1), "=r"(r2), "=r"(r3) : "r"(addr))

#define MMA_BF16(c0,c1,c2,c3,a0,a1,a2,a3,b0,b1) \
    asm volatile("mma.sync.aligned.m16n8k16.row.col.f32.bf16.bf16.f32 " \
        "{%0,%1,%2,%3}, {%4,%5,%6,%7}, {%8,%9}, {%0,%1,%2,%3};" \
        : "+f"(c0), "+f"(c1), "+f"(c2), "+f"(c3) \
        : "r"(a0), "r"(a1), "r"(a2), "r"(a3), "r"(b0), "r"(b1))

// =====================================================================
// Generic tiled SGEMM body (SIMT, fp32).  A:[M,K] rm, B:[K,N] rm.
// TRANS=false: C:[M,N] rm (float or bf16), optional colScale[N].
// TRANS=true : C is bf16 [Nglobal][KD] and stores C[n][k] = acc^T.
// =====================================================================
template<int BM, int BN, int BK2, int TM, int TN, typename OutT, bool TRANS>
__device__ __forceinline__ void sgemm_body(
    const float* __restrict__ A, const float* __restrict__ B,
    OutT* __restrict__ C,
    int K, int ldA, int ldB, int ldC,
    int tileRow, int tileCol,
    const float* __restrict__ bias,
    const float* __restrict__ colScale)
{
    constexpr int THREADS = (BM/TM)*(BN/TN);
    constexpr bool BF16 = (sizeof(OutT) == 2);
    __shared__ float As[BK2][BM];
    __shared__ float Bs[BK2][BN];
    const int tid = threadIdx.x;
    const int tx = tid % (BN/TN);
    const int ty = tid / (BN/TN);

    A += (size_t)tileRow * BM * ldA;
    B += (size_t)tileCol * BN;
    if (!TRANS)
        C += (size_t)tileRow * BM * ldC + (size_t)tileCol * BN;

    constexpr int AVR = BK2/4;
    const int aRow = tid / AVR;
    const int aCol = (tid % AVR)*4;
    constexpr int ARS = THREADS / AVR;
    constexpr int AIT = BM / ARS;

    constexpr int BVR = BN/4;
    const int bRow = tid / BVR;
    const int bCol = (tid % BVR)*4;
    constexpr int BRS = THREADS / BVR;
    constexpr int BIT = BK2 / BRS;

    float4 aF[AIT], bF[BIT];
#pragma unroll
    for (int i=0;i<AIT;i++)
        aF[i] = *reinterpret_cast<const float4*>(&A[(size_t)(aRow+i*ARS)*ldA + aCol]);
#pragma unroll
    for (int i=0;i<BIT;i++)
        bF[i] = *reinterpret_cast<const float4*>(&B[(size_t)(bRow+i*BRS)*ldB + bCol]);

    float acc[TM][TN];
#pragma unroll
    for (int i=0;i<TM;i++)
#pragma unroll
        for (int j=0;j<TN;j++) acc[i][j] = 0.f;

    for (int kb = 0; kb < K; kb += BK2) {
        __syncthreads();
#pragma unroll
        for (int i=0;i<AIT;i++){
            As[aCol+0][aRow+i*ARS] = aF[i].x;
            As[aCol+1][aRow+i*ARS] = aF[i].y;
            As[aCol+2][aRow+i*ARS] = aF[i].z;
            As[aCol+3][aRow+i*ARS] = aF[i].w;
        }
#pragma unroll
        for (int i=0;i<BIT;i++)
            *reinterpret_cast<float4*>(&Bs[bRow+i*BRS][bCol]) = bF[i];
        __syncthreads();

        if (kb + BK2 < K) {
#pragma unroll
            for (int i=0;i<AIT;i++)
                aF[i] = *reinterpret_cast<const float4*>(
                    &A[(size_t)(aRow+i*ARS)*ldA + (kb+BK2) + aCol]);
#pragma unroll
            for (int i=0;i<BIT;i++)
                bF[i] = *reinterpret_cast<const float4*>(
                    &B[(size_t)(kb+BK2+bRow+i*BRS)*ldB + bCol]);
        }

#pragma unroll
        for (int k=0;k<BK2;k++){
            float ra[TM], rb[TN];
#pragma unroll
            for (int i=0;i<TM;i+=4){
                float4 v = *reinterpret_cast<const float4*>(&As[k][ty*TM+i]);
                ra[i]=v.x; ra[i+1]=v.y; ra[i+2]=v.z; ra[i+3]=v.w;
            }
#pragma unroll
            for (int j=0;j<TN;j+=4){
                float4 v = *reinterpret_cast<const float4*>(&Bs[k][tx*TN+j]);
                rb[j]=v.x; rb[j+1]=v.y; rb[j+2]=v.z; rb[j+3]=v.w;
            }
#pragma unroll
            for (int i=0;i<TM;i++)
#pragma unroll
                for (int j=0;j<TN;j++)
                    acc[i][j] = fmaf(ra[i], rb[j], acc[i][j]);
        }
    }

    if constexpr (TRANS) {
#pragma unroll
        for (int i=0;i<TM;i++){
            const int row = tileRow*BM + ty*TM + i;      // k index
            const float bv = bias ? bias[row] : 0.f;
#pragma unroll
            for (int j=0;j<TN;j++){
                const int col = tileCol*BN + tx*TN + j;  // n index
                C[(size_t)col * KD + row] = __float2bfloat16(acc[i][j] + bv);
            }
        }
    } else {
#pragma unroll
        for (int i=0;i<TM;i++){
            const int row = ty*TM + i;
            const float bv = bias ? bias[tileRow*BM + row] : 0.f;
#pragma unroll
            for (int j=0;j<TN;j+=4){
                const int col = tx*TN + j;
                float4 o;
                o.x = acc[i][j+0] + bv;
                o.y = acc[i][j+1] + bv;
                o.z = acc[i][j+2] + bv;
                o.w = acc[i][j+3] + bv;
                if (colScale) {
                    const float4 cs = *reinterpret_cast<const float4*>(
                        &colScale[tileCol*BN + col]);
                    o.x *= cs.x; o.y *= cs.y; o.z *= cs.z; o.w *= cs.w;
                }
                if constexpr (!BF16) {
                    *reinterpret_cast<float4*>(&C[(size_t)row*ldC + col]) = o;
                } else {
                    __nv_bfloat162 p0 = __float22bfloat162_rn(make_float2(o.x, o.y));
                    __nv_bfloat162 p1 = __float22bfloat162_rn(make_float2(o.z, o.w));
                    uint2 u;
                    u.x = reinterpret_cast<uint32_t&>(p0);
                    u.y = reinterpret_cast<uint32_t&>(p1);
                    *reinterpret_cast<uint2*>(&C[(size_t)row*ldC + col]) = u;
                }
            }
        }
    }
}

// =====================================================================
// Kernel 1: f/g projections -> transposed bf16 [n][32]
// =====================================================================
__global__ __launch_bounds__(256) void proj_fg_kernel(
    const float* __restrict__ x1, const float* __restrict__ x2,
    const float* __restrict__ f_w, const float* __restrict__ f_b,
    const float* __restrict__ g_w, const float* __restrict__ g_b)
{
    const int z  = blockIdx.z;
    const int br = z >> 2, b = z & 3;
    const int fg = blockIdx.y;
    const float* W    = fg ? g_w : f_w;
    const float* bias = fg ? g_b : f_b;
    const float* X    = (br ? x2 : x1) + (size_t)b * CH * NPIX;
    __nv_bfloat16* C = fg ? &g_gT[z][0][0] : &g_fT[z][0][0];
    sgemm_body<32,128,32,4,4,__nv_bfloat16,true>(W, X, C, CH, CH, NPIX, 0,
                                                 0, blockIdx.x, bias, nullptr);
}

// =====================================================================
// Kernel 2 (fused): scores (HMMA bf16) + softmax-max/exp + transposed
// bf16 P' write + invsum.  (unchanged from round 4)
// =====================================================================
#define FLD   40
#define FSM_FT   0u
#define FSM_G    5120u
#define FSM_GSZ  20480u
#define FSM_ST   46080u
#define FSM_RED  82944u
#define FSM_TOTAL 83968u

__global__ __launch_bounds__(256) void fused_sm_kernel()
{
    extern __shared__ __align__(16) char sm[];
    const uint32_t smBase = smem_u32(sm);
    float* red = reinterpret_cast<float*>(sm + FSM_RED);

    const int tid  = threadIdx.x;
    const int lane = tid & 31, wid = tid >> 5;
    const int z  = blockIdx.y;
    const int n0 = blockIdx.x * 64;
    const int warpM = wid >> 2;
    const int warpN = wid & 3;
    const int qg = lane >> 2, tq = lane & 3;

    {
        const int row = tid >> 2, ch = tid & 3;
        CP_ASYNC16(smBase + FSM_FT + (uint32_t)((row*FLD + ch*8)*2),
                   (const char*)&g_fT[z][n0 + row][ch*8]);
    }
    CP_ASYNC_COMMIT();

    const int lm  = lane & 15;
    const int aco = (lane >= 16) ? 8 : 0;
    uint32_t aAddr[2];
#pragma unroll
    for (int mt=0; mt<2; mt++)
        aAddr[mt] = smBase + FSM_FT +
            (uint32_t)(((warpM*32 + mt*16 + lm)*FLD + aco)*2);
    const int bro = (lane & 7) + ((lane >= 16) ? 8 : 0);
    const int bco = (lane & 8) ? 8 : 0;
    uint32_t bOff[4];
#pragma unroll
    for (int p=0; p<4; p++)
        bOff[p] = (uint32_t)(((warpN*64 + p*16 + bro)*FLD + bco)*2);

    const int grow = tid >> 2, gch = tid & 3;

    float rmax[4], rsum[4];
#pragma unroll
    for (int i=0;i<4;i++){ rmax[i] = -3.4e38f; rsum[i] = 0.f; }

    const float CEXP = 0.17677669529663688f * 1.4426950408889634f;

    for (int pass = 0; pass < 2; ++pass) {
        {
            const char* src = (const char*)&g_gT[z][0][0];
#pragma unroll
            for (int i=0;i<4;i++)
                CP_ASYNC16(smBase + FSM_G + (uint32_t)(((grow+i*64)*FLD + gch*8)*2),
                           src + (size_t)(grow + i*64)*64 + gch*16);
            CP_ASYNC_COMMIT();
        }
        for (int t = 0; t < 16; ++t) {
            if (t < 15) {
                const uint32_t dst = smBase + FSM_G + (uint32_t)((t+1)&1)*FSM_GSZ;
                const char* src = (const char*)&g_gT[z][(t+1)*256][0];
#pragma unroll
                for (int i=0;i<4;i++)
                    CP_ASYNC16(dst + (uint32_t)(((grow+i*64)*FLD + gch*8)*2),
                               src + (size_t)(grow + i*64)*64 + gch*16);
                CP_ASYNC_COMMIT();
                CP_ASYNC_WAIT_1();
            } else {
                CP_ASYNC_WAIT_0();
            }
            __syncthreads();

            const uint32_t gb = smBase + FSM_G + (uint32_t)(t&1)*FSM_GSZ;
            float acc[2][8][4];
#pragma unroll
            for (int mt=0;mt<2;mt++)
#pragma unroll
                for (int nt=0;nt<8;nt++)
#pragma unroll
                    for (int c=0;c<4;c++) acc[mt][nt][c] = 0.f;

#pragma unroll
            for (int ks = 0; ks < 2; ++ks) {
                uint32_t a[2][4];
#pragma unroll
                for (int mt=0; mt<2; mt++)
                    LDSM_X4(a[mt][0], a[mt][1], a[mt][2], a[mt][3],
                            aAddr[mt] + ks*32);
                uint32_t bb[4][4];
#pragma unroll
                for (int p=0; p<4; p++)
                    LDSM_X4(bb[p][0], bb[p][1], bb[p][2], bb[p][3],
                            gb + bOff[p] + ks*32);
#pragma unroll
                for (int mt=0; mt<2; mt++)
#pragma unroll
                    for (int nt=0; nt<8; nt++) {
                        const uint32_t b0 = bb[nt>>1][(nt&1)*2];
                        const uint32_t b1 = bb[nt>>1][(nt&1)*2+1];
                        MMA_BF16(acc[mt][nt][0], acc[mt][nt][1],
                                 acc[mt][nt][2], acc[mt][nt][3],
                                 a[mt][0], a[mt][1], a[mt][2], a[mt][3], b0, b1);
                    }
            }

            if (pass == 0) {
#pragma unroll
                for (int mt=0;mt<2;mt++)
#pragma unroll
                    for (int nt=0;nt<8;nt++)
#pragma unroll
                        for (int c=0;c<4;c++)
                            rmax[mt*2 + (c>>1)] =
                                fmaxf(rmax[mt*2 + (c>>1)], acc[mt][nt][c]);
                __syncthreads();
            } else {
                __nv_bfloat16* stg = reinterpret_cast<__nv_bfloat16*>(sm + FSM_ST);
#pragma unroll
                for (int mt=0;mt<2;mt++)
#pragma unroll
                    for (int nt=0;nt<8;nt++)
#pragma unroll
                        for (int c=0;c<4;c++){
                            const int idx = mt*2 + (c>>1);
                            const float p = ex2f((acc[mt][nt][c] - rmax[idx]) * CEXP);
                            rsum[idx] += p;
                            const int ml = warpN*64 + nt*8 + tq*2 + (c&1);
                            const int nl = warpM*32 + mt*16 + qg + (c>>1)*8;
                            stg[ml*72 + nl] = __float2bfloat16(p);
                        }
                __syncthreads();
                const int ch = tid & 7;
#pragma unroll
                for (int i=0;i<8;i++){
                    const int ml = (tid>>3) + i*32;
                    const uint4 v = *reinterpret_cast<const uint4*>(
                        sm + FSM_ST + (uint32_t)((ml*72 + ch*8)*2));
                    *reinterpret_cast<uint4*>(&g_Pt[z][t*256 + ml][n0 + ch*8]) = v;
                }
            }
        }

        if (pass == 0) {
#pragma unroll
            for (int i=0;i<4;i++){
                float v = rmax[i];
                v = fmaxf(v, __shfl_xor_sync(0xffffffffu, v, 1));
                v = fmaxf(v, __shfl_xor_sync(0xffffffffu, v, 2));
                rmax[i] = v;
            }
            if (tq == 0) {
#pragma unroll
                for (int i=0;i<4;i++){
                    const int r = warpM*32 + (i>>1)*16 + qg + (i&1)*8;
                    red[r*4 + warpN] = rmax[i];
                }
            }
            __syncthreads();
#pragma unroll
            for (int i=0;i<4;i++){
                const int r = warpM*32 + (i>>1)*16 + qg + (i&1)*8;
                rmax[i] = fmaxf(fmaxf(red[r*4+0], red[r*4+1]),
                                fmaxf(red[r*4+2], red[r*4+3]));
            }
            __syncthreads();
        }
    }

#pragma unroll
    for (int i=0;i<4;i++){
        float v = rsum[i];
        v += __shfl_xor_sync(0xffffffffu, v, 1);
        v += __shfl_xor_sync(0xffffffffu, v, 2);
        rsum[i] = v;
    }
    __syncthreads();
    if (tq == 0) {
#pragma unroll
        for (int i=0;i<4;i++){
            const int r = warpM*32 + (i>>1)*16 + qg + (i&1)*8;
            red[r*4 + warpN] = rsum[i];
        }
    }
    __syncthreads();
    if (warpN == 0 && tq == 0) {
#pragma unroll
        for (int i=0;i<4;i++){
            const int r = warpM*32 + (i>>1)*16 + qg + (i&1)*8;
            const float s = red[r*4+0] + red[r*4+1] + red[r*4+2] + red[r*4+3];
            g_invsum[z][n0 + r] = 1.0f / s;
        }
    }
}

// =====================================================================
// Kernel 3: h projection -> bf16, columns scaled by invsum[n]
// =====================================================================
__global__ __launch_bounds__(256) void proj_h_kernel(
    const float* __restrict__ x1, const float* __restrict__ x2,
    const float* __restrict__ h1w, const float* __restrict__ h1b,
    const float* __restrict__ h2w, const float* __restrict__ h2b)
{
    const int z  = blockIdx.z;
    const int br = z >> 2, b = z & 3;
    const float* W    = br ? h2w : h1w;
    const float* bias = br ? h2b : h1b;
    const float* X    = (br ? x2 : x1) + (size_t)b * CH * NPIX;
    sgemm_body<128,128,8,8,8,__nv_bfloat16,false>(
        W, X, &g_Hb[z][0][0], CH, CH, NPIX, NPIX,
        blockIdx.y, blockIdx.x, bias, &g_invsum[z][0]);
}

// =====================================================================
// Kernel 4: out[z] = gamma * (H' @ P') + x  via mma.sync bf16 (HMMA).
// 3-stage cp.async ring (prefetch distance 2), one sync per K-iter,
// __launch_bounds__(256,2) pins 2 CTAs/SM.
// =====================================================================
#define BK      64
#define LDSS    72
#define STGB    (128*LDSS*2)             // 18432 bytes per operand per stage
#define NSTG    3
#define OUT_SMEM (NSTG*2*STGB)           // 110592

__global__ void __launch_bounds__(256, 2) out_mma_kernel(
    const float* __restrict__ x1, const float* __restrict__ x2,
    const float* __restrict__ gamma1, const float* __restrict__ gamma2,
    float* __restrict__ out)
{
    extern __shared__ char smo[];
    const uint32_t smBase = smem_u32(smo);

    const int tid = threadIdx.x;
    const int wid = tid >> 5, lane = tid & 31;
    const int z = blockIdx.z, br = z >> 2, b = z & 3;
    const int mBase = blockIdx.x * 128;
    const int cBase = blockIdx.y * 128;
    const float* X = (br ? x2 : x1) + (size_t)b * CH * NPIX;
    const float gamma = (br ? gamma2 : gamma1)[0];

    // loader mapping: 2 threads per row, 32 elems (64B) each
    const int lrow = tid >> 1;
    const int lcol = (tid & 1) * 32;
    const char* gAp = (const char*)(&g_Hb[z][cBase + lrow][lcol]);
    const char* gBp = (const char*)(&g_Pt[z][mBase + lrow][lcol]);
    const uint32_t ldOff = (uint32_t)((lrow*LDSS + lcol)*2);

    // ldmatrix lane offsets (within a stage slot)
    const int warpM = wid >> 2;
    const int warpN = wid & 3;
    const int lm  = lane & 15;
    const int aco = (lane >= 16) ? 8 : 0;
    uint32_t aOff[4];
#pragma unroll
    for (int mt=0; mt<4; mt++)
        aOff[mt] = (uint32_t)(((warpM*64 + mt*16 + lm)*LDSS + aco)*2);
    const int bro = (lane & 7) + ((lane >= 16) ? 8 : 0);
    const int bco = (lane & 8) ? 8 : 0;
    uint32_t bOff[2];
#pragma unroll
    for (int p=0; p<2; p++)
        bOff[p] = (uint32_t)(((warpN*32 + p*16 + bro)*LDSS + bco)*2) + STGB;

    float acc[4][4][4];
#pragma unroll
    for (int i=0;i<4;i++)
#pragma unroll
        for (int j=0;j<4;j++)
#pragma unroll
            for (int k=0;k<4;k++) acc[i][j][k] = 0.f;

    // ---- prologue: stages 0, 1 (two commit groups) ----
#pragma unroll
    for (int st=0; st<2; ++st) {
        const uint32_t slot = smBase + (uint32_t)st * (2*STGB);
        const char* sa = gAp + (size_t)st * (BK*2);
        const char* sb = gBp + (size_t)st * (BK*2);
#pragma unroll
        for (int j=0;j<4;j++) CP_ASYNC16(slot + ldOff + j*16, sa + j*16);
#pragma unroll
        for (int j=0;j<4;j++) CP_ASYNC16(slot + STGB + ldOff + j*16, sb + j*16);
        CP_ASYNC_COMMIT();
    }

    int slotC = 0;   // compute slot = it % 3
    int slotP = 2;   // prefetch slot = (it+2) % 3
    for (int it = 0; it < NPIX/BK; ++it) {
        CP_ASYNC_WAIT_1();          // stage it arrived (stage it+1 may be pending)
        __syncthreads();            // visibility + all warps done with slot it-1

        // prefetch stage it+2 into slotP (overwrites stage it-1's slot)
        if (it + 2 < NPIX/BK) {
            const uint32_t slot = smBase + (uint32_t)slotP * (2*STGB);
            const char* sa = gAp + (size_t)(it+2) * (BK*2);
            const char* sb = gBp + (size_t)(it+2) * (BK*2);
#pragma unroll
            for (int j=0;j<4;j++) CP_ASYNC16(slot + ldOff + j*16, sa + j*16);
#pragma unroll
            for (int j=0;j<4;j++) CP_ASYNC16(slot + STGB + ldOff + j*16, sb + j*16);
        }
        CP_ASYNC_COMMIT();          // commit (possibly empty) to keep group count aligned

        const uint32_t sb = smBase + (uint32_t)slotC * (2*STGB);
#pragma unroll
        for (int ks = 0; ks < 4; ++ks) {
            uint32_t a[4][4];
#pragma unroll
            for (int mt=0; mt<4; mt++)
                LDSM_X4(a[mt][0], a[mt][1], a[mt][2], a[mt][3],
                        sb + aOff[mt] + ks*32);
            uint32_t bb[2][4];
#pragma unroll
            for (int p=0; p<2; p++)
                LDSM_X4(bb[p][0], bb[p][1], bb[p][2], bb[p][3],
                        sb + bOff[p] + ks*32);
#pragma unroll
            for (int mt=0; mt<4; mt++)
#pragma unroll
                for (int nt=0; nt<4; nt++) {
                    const uint32_t b0 = bb[nt>>1][(nt&1)*2];
                    const uint32_t b1 = bb[nt>>1][(nt&1)*2+1];
                    MMA_BF16(acc[mt][nt][0], acc[mt][nt][1],
                             acc[mt][nt][2], acc[mt][nt][3],
                             a[mt][0], a[mt][1], a[mt][2], a[mt][3], b0, b1);
                }
        }

        slotC = (slotC == 2) ? 0 : slotC + 1;
        slotP = (slotP == 2) ? 0 : slotP + 1;
    }

    // ---- epilogue: out = gamma*acc + x ----
    const int g  = lane >> 2;
    const int tq = lane & 3;
    float* Cz = out + (size_t)z * CH * NPIX;
#pragma unroll
    for (int mt=0; mt<4; mt++) {
        const int row = cBase + warpM*64 + mt*16 + g;
#pragma unroll
        for (int nt=0; nt<4; nt++) {
            const int col = mBase + warpN*32 + nt*8 + tq*2;
            {
                const float2 xv = *reinterpret_cast<const float2*>(
                    &X[(size_t)row*NPIX + col]);
                float2 o;
                o.x = fmaf(gamma, acc[mt][nt][0], xv.x);
                o.y = fmaf(gamma, acc[mt][nt][1], xv.y);
                *reinterpret_cast<float2*>(&Cz[(size_t)row*NPIX + col]) = o;
            }
            {
                const float2 xv = *reinterpret_cast<const float2*>(
                    &X[(size_t)(row+8)*NPIX + col]);
                float2 o;
                o.x = fmaf(gamma, acc[mt][nt][2], xv.x);
                o.y = fmaf(gamma, acc[mt][nt][3], xv.y);
                *reinterpret_cast<float2*>(&Cz[(size_t)(row+8)*NPIX + col]) = o;
            }
        }
    }
}

// =====================================================================
extern "C" void kernel_launch(void* const* d_in, const int* in_sizes, int n_in,
                              void* d_out, int out_size)
{
    const float* x1     = (const float*)d_in[0];
    const float* x2     = (const float*)d_in[1];
    const float* f_w    = (const float*)d_in[2];
    const float* f_b    = (const float*)d_in[3];
    const float* g_w    = (const float*)d_in[4];
    const float* g_b    = (const float*)d_in[5];
    const float* h1_w   = (const float*)d_in[6];
    const float* h1_b   = (const float*)d_in[7];
    const float* h2_w   = (const float*)d_in[8];
    const float* h2_b   = (const float*)d_in[9];
    const float* gamma1 = (const float*)d_in[10];
    const float* gamma2 = (const float*)d_in[11];
    float* out = (float*)d_out;

    cudaFuncSetAttribute(fused_sm_kernel,
                         cudaFuncAttributeMaxDynamicSharedMemorySize, FSM_TOTAL);
    cudaFuncSetAttribute(out_mma_kernel,
                         cudaFuncAttributeMaxDynamicSharedMemorySize, OUT_SMEM);

    proj_fg_kernel <<<dim3(32, 2, NZ), 256>>>(x1, x2, f_w, f_b, g_w, g_b);
    fused_sm_kernel<<<dim3(64, NZ), 256, FSM_TOTAL>>>();
    proj_h_kernel  <<<dim3(32, 2, NZ), 256>>>(x1, x2, h1_w, h1_b, h2_w, h2_b);
    out_mma_kernel <<<dim3(32, 2, NZ), 256, OUT_SMEM>>>(x1, x2, gamma1, gamma2, out);
}